// round 4
// baseline (speedup 1.0000x reference)
#include <cuda_runtime.h>
#include <cuda_bf16.h>

// Problem constants
#define SDIM     785          // seq incl. CLS
#define SLABSZ   616225       // 785*785
#define NP       784
#define NL       12
#define NB       4
#define NH       12
#define NSLAB    (NL*NB*NH)   // 576
#define KTH      588
#define LN_EPS   1e-5f
#define CHUNKS   4
#define GPC      49           // groups per chunk

// Scratch accumulator: g_sums[b][c] for column j = c+1.
// Zero-initialized at module load; finalize_kernel re-zeroes it after use,
// so every kernel_launch invocation (and every graph replay) starts from 0.
__device__ float g_sums[NB * NP];

// ---------------------------------------------------------------------------
// Kernel 1: vectorized column-sum + distributed edge-row correction.
// 4-row groups start at rows with (m + r) % 4 == 0 so per-row float shifts
// are statically {0,1,2,3}: every load is an aligned LDG.128. Thread t owns
// float4 slot t; element (lane e, shift s) -> column 4t + e - s, accumulator
// d = e - s + 3 in a fixed 7-wide window [4t-3, 4t+3].
// Edge rows not covered by aligned groups are distributed one-per-chunk-block.
// ---------------------------------------------------------------------------
__global__ __launch_bounds__(224) void colsum_vec(const float* __restrict__ att) {
    const int blk   = blockIdx.x;           // 0 .. NSLAB*CHUNKS-1
    const int chunk = blk & (CHUNKS - 1);
    const int m     = blk >> 2;             // slab 0..575
    const int t     = threadIdx.x;

    const int b       = (m / NH) & 3;       // m = l*48 + b*12 + h
    const int r_first = (4 - (m & 3)) & 3;  // first row with shift 0
    const int Gm      = (785 - r_first) >> 2;
    const int g0      = chunk * GPC;
    int gcnt = Gm - g0;
    if (gcnt > GPC) gcnt = GPC;
    float* gs = &g_sums[b * NP];

    if (t <= 196 && gcnt > 0) {
        const float* fp = att + (size_t)m * SLABSZ
                              + (size_t)(r_first + 4 * g0) * SDIM;   // 16B-aligned

        float a0 = 0.f, a1 = 0.f, a2 = 0.f, a3 = 0.f, a4 = 0.f, a5 = 0.f, a6 = 0.f;

        #pragma unroll 2
        for (int g = 0; g < gcnt; ++g) {
            const float4 x = __ldcs((const float4*)(fp)        + t);  // shift 0
            const float4 y = __ldcs((const float4*)(fp +  784) + t);  // shift 1
            const float4 z = __ldcs((const float4*)(fp + 1568) + t);  // shift 2
            const float4 w = __ldcs((const float4*)(fp + 2352) + t);  // shift 3

            a3 += x.x; a4 += x.y; a5 += x.z; a6 += x.w;   // cols 4t .. 4t+3
            a2 += y.x; a3 += y.y; a4 += y.z; a5 += y.w;   // cols 4t-1 .. 4t+2
            a1 += z.x; a2 += z.y; a3 += z.z; a4 += z.w;   // cols 4t-2 .. 4t+1
            a0 += w.x; a1 += w.y; a2 += w.z; a3 += w.w;   // cols 4t-3 .. 4t
            fp += 4 * SDIM;
        }

        const float acc[7] = {a0, a1, a2, a3, a4, a5, a6};
        const int cbase = 4 * t - 3;
        #pragma unroll
        for (int d = 0; d < 7; ++d) {
            const int c = cbase + d;              // column j in [1,784]
            if (c >= 1 && c <= NP) atomicAdd(&gs[c - 1], acc[d]);
        }
    }

    // Edge-row correction, one row per chunk-block:
    //   m%4==0: groups cover 0..783  -> -row0, +row784        (2 rows)
    //   m%4==1: cover 3..782         -> +rows 1,2,783,784     (4 rows)
    //   m%4==2: cover 2..781         -> +rows 1,782,783,784   (4 rows)
    //   m%4==3: cover 1..784         -> nothing
    {
        const int mm = m & 3;
        int row = -1; float sgn = 1.f;
        if (mm == 0) {
            if (chunk == 0) { row = 0; sgn = -1.f; }
            else if (chunk == 1) { row = 784; }
        } else if (mm == 1) {
            const int rows[4] = {1, 2, 783, 784};
            row = rows[chunk];
        } else if (mm == 2) {
            const int rows[4] = {1, 782, 783, 784};
            row = rows[chunk];
        }
        if (row >= 0) {
            const float* rp = att + (size_t)m * SLABSZ + (size_t)row * SDIM;
            for (int c = t; c < NP; c += blockDim.x)
                atomicAdd(&gs[c], sgn * __ldg(rp + (c + 1)));
        }
    }
}

// ---------------------------------------------------------------------------
// Kernel 2: LayerNorm + sigmoid + radix-select kth-smallest + mask.
// Also resets g_sums to zero for the next replay.
// ---------------------------------------------------------------------------
__device__ __forceinline__ float block_reduce_sum(float v, float* red) {
    #pragma unroll
    for (int o = 16; o > 0; o >>= 1) v += __shfl_xor_sync(0xFFFFFFFFu, v, o);
    const int wid = threadIdx.x >> 5, lid = threadIdx.x & 31;
    if (lid == 0) red[wid] = v;
    __syncthreads();
    if (wid == 0) {
        v = red[lid];
        #pragma unroll
        for (int o = 16; o > 0; o >>= 1) v += __shfl_xor_sync(0xFFFFFFFFu, v, o);
        if (lid == 0) red[0] = v;
    }
    __syncthreads();
    float r = red[0];
    __syncthreads();
    return r;
}

__global__ __launch_bounds__(1024) void finalize_kernel(const float* __restrict__ gamma,
                                                        const float* __restrict__ beta,
                                                        float* __restrict__ out) {
    __shared__ float red[32];
    __shared__ int   hist[256];
    __shared__ unsigned s_prefix;
    __shared__ int      s_k;

    const int b = blockIdx.x;
    const int t = threadIdx.x;
    const int wid = t >> 5, lid = t & 31;
    const bool active = (t < NP);

    float s = 0.0f;
    if (active) {
        s = g_sums[b * NP + t] * (1.0f / 144.0f);
        g_sums[b * NP + t] = 0.0f;          // reset for next graph replay
    }

    const float mu = block_reduce_sum(s, red) * (1.0f / (float)NP);
    float d = active ? (s - mu) : 0.0f;
    const float rstd = rsqrtf(block_reduce_sum(d * d, red) * (1.0f / (float)NP) + LN_EPS);

    float p = 0.0f;
    unsigned key = 0u;
    if (active) {
        float ln = d * rstd * gamma[t] + beta[t];
        p   = 1.0f / (1.0f + expf(-ln));
        key = __float_as_uint(p);           // monotone: p > 0
    }

    if (t == 0) { s_prefix = 0u; s_k = KTH; }
    __syncthreads();

    #pragma unroll
    for (int pass = 0; pass < 4; ++pass) {
        const int shift = 24 - 8 * pass;
        const unsigned hi_mask = (pass == 0) ? 0u : (0xFFFFFFFFu << (shift + 8));

        if (t < 256) hist[t] = 0;
        __syncthreads();

        const unsigned prefix = s_prefix;
        const int k = s_k;
        if (active && ((key & hi_mask) == prefix))
            atomicAdd(&hist[(key >> shift) & 255], 1);
        __syncthreads();

        if (wid == 0) {
            int sub = 0;
            #pragma unroll
            for (int i = 0; i < 8; ++i) sub += hist[lid * 8 + i];
            int inc = sub;
            #pragma unroll
            for (int o = 1; o < 32; o <<= 1) {
                int v = __shfl_up_sync(0xFFFFFFFFu, inc, o);
                if (lid >= o) inc += v;
            }
            const int ex = inc - sub;
            if (ex < k && k <= inc) {           // exactly one lane
                int cum = ex;
                #pragma unroll
                for (int i = 0; i < 8; ++i) {
                    const int h = hist[lid * 8 + i];
                    if (k <= cum + h) {
                        s_prefix = prefix | ((unsigned)(lid * 8 + i) << shift);
                        s_k = k - cum;
                        break;
                    }
                    cum += h;
                }
            }
        }
        __syncthreads();
    }

    const float thr = __uint_as_float(s_prefix);   // exact kth-smallest p
    if (active) out[b * NP + t] = (p > thr) ? 1.0f : 0.0f;
}

// ---------------------------------------------------------------------------
// Launch contract
// ---------------------------------------------------------------------------
extern "C" void kernel_launch(void* const* d_in, const int* in_sizes, int n_in,
                              void* d_out, int out_size) {
    const float* att   = (const float*)d_in[0];   // [12,4,12,785,785] f32
    const float* gamma = (const float*)d_in[1];   // [784] f32
    const float* beta  = (const float*)d_in[2];   // [784] f32
    float* out = (float*)d_out;                   // [4,784] f32

    colsum_vec<<<NSLAB * CHUNKS, 224>>>(att);
    finalize_kernel<<<NB, 1024>>>(gamma, beta, out);
}